// round 1
// baseline (speedup 1.0000x reference)
#include <cuda_runtime.h>

#define B_ 2
#define L_ 4096
#define C_ 512
#define H_ 8
#define D_ 64
#define THREE_C 1536

static __device__ float g_kqv[(size_t)B_ * L_ * THREE_C];   // [B*L, 3C] : k | q | v
static __device__ float g_attn[(size_t)B_ * L_ * C_];       // [B*L, C]

// ============================================================================
// SGEMM: C[M,N] = A[M,K] @ B[K,N] (+ bias). BM=BN=64, BK=16, 256 thr, 4x4/thr
// ============================================================================
__global__ __launch_bounds__(256) void sgemm_kernel(
    const float* __restrict__ A, const float* __restrict__ Bm,
    const float* __restrict__ bias, float* __restrict__ Cm,
    int M, int N, int K)
{
    __shared__ float As[16][64];
    __shared__ float Bs[16][64];

    const int tid = threadIdx.x;
    const int bm = blockIdx.y * 64;
    const int bn = blockIdx.x * 64;
    const int tx = tid & 15, ty = tid >> 4;

    float acc[4][4];
#pragma unroll
    for (int i = 0; i < 4; ++i)
#pragma unroll
        for (int j = 0; j < 4; ++j) acc[i][j] = 0.f;

    const int ar = tid >> 2, ac = (tid & 3) << 2;   // A tile: 64 rows x 16 k
    const int br = tid >> 4, bc = (tid & 15) << 2;  // B tile: 16 k x 64 cols

    for (int k0 = 0; k0 < K; k0 += 16) {
        float4 a4 = *(const float4*)(A + (size_t)(bm + ar) * K + k0 + ac);
        As[ac + 0][ar] = a4.x; As[ac + 1][ar] = a4.y;
        As[ac + 2][ar] = a4.z; As[ac + 3][ar] = a4.w;
        *(float4*)(&Bs[br][bc]) = *(const float4*)(Bm + (size_t)(k0 + br) * N + bn + bc);
        __syncthreads();
#pragma unroll
        for (int k = 0; k < 16; ++k) {
            float4 av = *(const float4*)(&As[k][ty << 2]);
            float4 bv = *(const float4*)(&Bs[k][tx << 2]);
            float aa[4] = {av.x, av.y, av.z, av.w};
            float bb[4] = {bv.x, bv.y, bv.z, bv.w};
#pragma unroll
            for (int i = 0; i < 4; ++i)
#pragma unroll
                for (int j = 0; j < 4; ++j)
                    acc[i][j] = fmaf(aa[i], bb[j], acc[i][j]);
        }
        __syncthreads();
    }

#pragma unroll
    for (int i = 0; i < 4; ++i) {
        int row = bm + (ty << 2) + i;
        int col = bn + (tx << 2);
        float4 o;
        o.x = acc[i][0]; o.y = acc[i][1]; o.z = acc[i][2]; o.w = acc[i][3];
        if (bias) {
            o.x += bias[col]; o.y += bias[col + 1];
            o.z += bias[col + 2]; o.w += bias[col + 3];
        }
        *(float4*)(Cm + (size_t)row * N + col) = o;
    }
}

// ============================================================================
// Flash attention (fp32, exact online softmax).
// Grid: B*H*(L/64). Block: 256 thr = 8 warps. Warp w owns q-rows [8w, 8w+8).
// Lane owns columns {lane, lane+32} of both S (over K-tile) and O (over D).
// ============================================================================
#define BQ 64
#define KTILE 64
// smem: Qs[64][64] + KT[64][65] + Vs[64][64] + Ps[64][64]
#define ATTN_SMEM_FLOATS (64 * 64 + 64 * 65 + 64 * 64 + 64 * 64)
#define ATTN_SMEM_BYTES (ATTN_SMEM_FLOATS * 4)

__global__ __launch_bounds__(256) void attn_kernel(
    const float* __restrict__ kqv, float* __restrict__ attn_out)
{
    const float SCALE = 22.627416997969522f;  // sqrt(512)

    const int bid = blockIdx.x;
    const int qtile = bid & 63;          // L/BQ = 64
    const int bh = bid >> 6;
    const int h = bh & (H_ - 1);
    const int b = bh >> 3;

    const int tid = threadIdx.x;
    const int lane = tid & 31;
    const int warp = tid >> 5;
    const int q0 = warp * 8;

    extern __shared__ float sm[];
    float* Qs = sm;                  // [64][64]
    float* KT = Qs + 64 * 64;        // [64][65]  (d-major, transposed K)
    float* Vs = KT + 64 * 65;        // [64][64]
    float* Ps = Vs + 64 * 64;        // [64][64]

    const size_t row_base = (size_t)b * L_ * THREE_C;
    const float* Kp = kqv + row_base + (size_t)h * D_;            // k chunk
    const float* Qp = kqv + row_base + C_ + (size_t)h * D_;       // q chunk
    const float* Vp = kqv + row_base + 2 * C_ + (size_t)h * D_;   // v chunk

    // Load Q tile (pre-scaled): 64x64, coalesced
#pragma unroll
    for (int i = 0; i < 16; ++i) {
        int idx = tid + i * 256;
        int q = idx >> 6, d = idx & 63;
        Qs[q * 64 + d] = Qp[(size_t)(qtile * 64 + q) * THREE_C + d] * SCALE;
    }

    float m[8], rs[8], o0[8], o1[8];
#pragma unroll
    for (int q = 0; q < 8; ++q) {
        m[q] = -1e30f; rs[q] = 0.f; o0[q] = 0.f; o1[q] = 0.f;
    }

    const int dld = tid & 63;        // K-load: this thread's d
    const int jgrp = tid >> 6;       // 0..3

    for (int kt = 0; kt < L_ / KTILE; ++kt) {
        __syncthreads();   // previous iteration's smem reads done
        // Load K (transposed into KT) and V
#pragma unroll
        for (int i = 0; i < 16; ++i) {
            int j = jgrp * 16 + i;
            KT[dld * 65 + j] = Kp[(size_t)(kt * 64 + j) * THREE_C + dld];
        }
#pragma unroll
        for (int i = 0; i < 16; ++i) {
            int idx = tid + i * 256;
            int j = idx >> 6, dd = idx & 63;
            Vs[j * 64 + dd] = Vp[(size_t)(kt * 64 + j) * THREE_C + dd];
        }
        __syncthreads();

        // S = Q K^T  (each lane: 8 q-rows x 2 j-cols)
        float s0[8], s1[8];
#pragma unroll
        for (int q = 0; q < 8; ++q) { s0[q] = 0.f; s1[q] = 0.f; }

#pragma unroll
        for (int d4 = 0; d4 < 16; ++d4) {
            float k0[4], k1[4];
#pragma unroll
            for (int i = 0; i < 4; ++i) {
                k0[i] = KT[(d4 * 4 + i) * 65 + lane];
                k1[i] = KT[(d4 * 4 + i) * 65 + lane + 32];
            }
#pragma unroll
            for (int q = 0; q < 8; ++q) {
                float4 qv = *(const float4*)(&Qs[(q0 + q) * 64 + d4 * 4]);
                s0[q] += qv.x * k0[0] + qv.y * k0[1] + qv.z * k0[2] + qv.w * k0[3];
                s1[q] += qv.x * k1[0] + qv.y * k1[1] + qv.z * k1[2] + qv.w * k1[3];
            }
        }

        // Online softmax update; stash P in smem (warp-private rows)
#pragma unroll
        for (int q = 0; q < 8; ++q) {
            float tmax = fmaxf(s0[q], s1[q]);
#pragma unroll
            for (int off = 16; off; off >>= 1)
                tmax = fmaxf(tmax, __shfl_xor_sync(0xFFFFFFFFu, tmax, off));
            float mnew = fmaxf(m[q], tmax);
            float p0 = __expf(s0[q] - mnew);
            float p1 = __expf(s1[q] - mnew);
            float ps = p0 + p1;
#pragma unroll
            for (int off = 16; off; off >>= 1)
                ps += __shfl_xor_sync(0xFFFFFFFFu, ps, off);
            float corr = __expf(m[q] - mnew);
            rs[q] = rs[q] * corr + ps;
            o0[q] *= corr;
            o1[q] *= corr;
            m[q] = mnew;
            Ps[(q0 + q) * 64 + lane] = p0;
            Ps[(q0 + q) * 64 + lane + 32] = p1;
        }
        __syncwarp();

        // O += P V
#pragma unroll
        for (int j4 = 0; j4 < 16; ++j4) {
            float v0[4], v1[4];
#pragma unroll
            for (int i = 0; i < 4; ++i) {
                v0[i] = Vs[(j4 * 4 + i) * 64 + lane];
                v1[i] = Vs[(j4 * 4 + i) * 64 + lane + 32];
            }
#pragma unroll
            for (int q = 0; q < 8; ++q) {
                float4 p = *(const float4*)(&Ps[(q0 + q) * 64 + j4 * 4]);
                o0[q] += p.x * v0[0] + p.y * v0[1] + p.z * v0[2] + p.w * v0[3];
                o1[q] += p.x * v1[0] + p.y * v1[1] + p.z * v1[2] + p.w * v1[3];
            }
        }
    }

    // Epilogue: attn_out[b, l, h*64 + d] = O / rowsum
#pragma unroll
    for (int q = 0; q < 8; ++q) {
        float inv = 1.f / rs[q];
        int ql = qtile * 64 + q0 + q;
        size_t base = ((size_t)(b * L_ + ql)) * C_ + h * D_;
        attn_out[base + lane] = o0[q] * inv;
        attn_out[base + lane + 32] = o1[q] * inv;
    }
}

// ============================================================================
// Launch
// ============================================================================
extern "C" void kernel_launch(void* const* d_in, const int* in_sizes, int n_in,
                              void* d_out, int out_size)
{
    const float* x     = (const float*)d_in[0];
    const float* w_kqv = (const float*)d_in[1];
    const float* w_out = (const float*)d_in[2];
    const float* b_out = (const float*)d_in[3];
    float* out = (float*)d_out;

    float *kqv_ptr, *attn_ptr;
    cudaGetSymbolAddress((void**)&kqv_ptr, g_kqv);
    cudaGetSymbolAddress((void**)&attn_ptr, g_attn);

    cudaFuncSetAttribute(attn_kernel,
                         cudaFuncAttributeMaxDynamicSharedMemorySize,
                         ATTN_SMEM_BYTES);

    // 1) kqv = x @ w_kqv          [8192,512] x [512,1536]
    sgemm_kernel<<<dim3(THREE_C / 64, (B_ * L_) / 64), 256>>>(
        x, w_kqv, nullptr, kqv_ptr, B_ * L_, THREE_C, C_);

    // 2) attention                 grid = B*H*(L/64) = 1024
    attn_kernel<<<B_ * H_ * (L_ / BQ), 256, ATTN_SMEM_BYTES>>>(kqv_ptr, attn_ptr);

    // 3) out = attn @ w_out + b    [8192,512] x [512,512]
    sgemm_kernel<<<dim3(C_ / 64, (B_ * L_) / 64), 256>>>(
        attn_ptr, w_out, b_out, out, B_ * L_, C_, C_);
}